// round 11
// baseline (speedup 1.0000x reference)
#include <cuda_runtime.h>
#include <cuda_fp16.h>
#include <cstdint>

// Problem constants
#define BATCH 4
#define SEQ   4096
#define DIM   1024
#define BT    (BATCH * SEQ)      // 16384

// GEMM tile config (fp16 operands, f32 accum)
// CTA tile 128x128, 4 warps, warp tile 64x64. Pipeline: 3 superstages, each =
// two BK=32 sub-stages (conflict-free layout), one barrier per superstage.
#define BM 128
#define BN 128
#define BK 32
#define ASTAGE (BM * BK)                 // halves per A sub-stage (8KB)
#define BSTAGE (BN * BK)
#define ASUP (2 * ASTAGE)                // superstage = 2 sub-stages (16KB)
#define BSUP (2 * BSTAGE)
#define SMEM_DYN (3 * (ASUP + BSUP) * 2) // 96 KB

// Epilogue modes
#define EPI_EXP   3   // exp -> fp16 out + deterministic partial row sums
#define EPI_NORM  4   // f32 out scaled by per-row inv sum
#define EPI_QKV   5   // fused QKV projection: z selects W + destination (z==2 transposed)

// Scratch (allocation-free rule: __device__ globals)
__device__ __half g_X [(long long)BT*DIM];
__device__ __half g_Wq[(long long)DIM*DIM];
__device__ __half g_Wk[(long long)DIM*DIM];
__device__ __half g_Wv[(long long)DIM*DIM];
__device__ __half g_Q [(long long)BT*DIM];
__device__ __half g_K [(long long)BT*DIM];
__device__ __half g_Vt[(long long)BT*DIM];         // [e][b*SEQ + t], ld = BT
__device__ __half g_P [(long long)BATCH*SEQ*SEQ];  // unnormalized exp probs, fp16
__device__ float  g_psum[64LL * BT];               // partial row sums [slot][row]
__device__ float  g_inv [BT];                      // 1 / row sum

__device__ __forceinline__ void cp16s(void* sm, const void* gm) {
    unsigned s = (unsigned)__cvta_generic_to_shared(sm);
    asm volatile("cp.async.cg.shared.global [%0], [%1], 16;" :: "r"(s), "l"(gm));
}

#define MMA_F16(acc, a0, a1, a2, a3, b0, b1)                                \
    asm volatile(                                                           \
        "mma.sync.aligned.m16n8k16.row.col.f32.f16.f16.f32 "                \
        "{%0,%1,%2,%3}, {%4,%5,%6,%7}, {%8,%9}, {%0,%1,%2,%3};"             \
        : "+f"((acc)[0]), "+f"((acc)[1]), "+f"((acc)[2]), "+f"((acc)[3])    \
        : "r"(a0), "r"(a1), "r"(a2), "r"(a3), "r"(b0), "r"(b1))

// f32 -> f16 conversion, 4 elems/thread (x input)
__global__ void to_half_kernel(const float* __restrict__ in, __half* __restrict__ out,
                               long long n) {
    long long i = ((long long)blockIdx.x * blockDim.x + threadIdx.x) * 4;
    if (i < n) {
        float4 v = *(const float4*)(in + i);
        __half2 h0 = __floats2half2_rn(v.x, v.y);
        __half2 h1 = __floats2half2_rn(v.z, v.w);
        *(uint2*)(out + i) = make_uint2(*(uint32_t*)&h0, *(uint32_t*)&h1);
    }
}

// All three weight converts in one launch: 1024 blocks per weight (1M elems each).
__global__ void w_to_half_kernel(const float* __restrict__ Wq,
                                 const float* __restrict__ Wk,
                                 const float* __restrict__ Wv) {
    int seg = blockIdx.x >> 10;
    const float* in = (seg == 0) ? Wq : (seg == 1) ? Wk : Wv;
    __half* out = (seg == 0) ? g_Wq : (seg == 1) ? g_Wk : g_Wv;
    long long i = (((long long)(blockIdx.x & 1023)) * 256 + threadIdx.x) * 4;
    float4 v = *(const float4*)(in + i);
    __half2 h0 = __floats2half2_rn(v.x, v.y);
    __half2 h1 = __floats2half2_rn(v.z, v.w);
    *(uint2*)(out + i) = make_uint2(*(uint32_t*)&h0, *(uint32_t*)&h1);
}

// Sum 64 partials per row, store reciprocal. grid = BT/256, block 256.
__global__ void rowinv_kernel(const float* __restrict__ psum, float* __restrict__ inv) {
    int row = blockIdx.x * 256 + threadIdx.x;
    float s = 0.f;
    #pragma unroll
    for (int j = 0; j < 64; j++) s += psum[(long long)j * BT + row];
    inv[row] = 1.f / s;
}

// C[M,N] = alpha * A[M,K] * B[N,K]^T, fp16 operands (K-contiguous), f32 accumulate.
// k-permutation trick: one LDS.128 per row gives thread tg k = {8tg..8tg+7};
// mma step0 uses {8tg..8tg+3}, step1 uses {8tg+4..8tg+7}; A/B slots agree.
template<int EPI>
__global__ void __launch_bounds__(128, 2) gemm_f16(
    const __half* __restrict__ A, const __half* __restrict__ B, void* __restrict__ Cv,
    float* __restrict__ aux,   // EPI_EXP: psum base; EPI_NORM: inv base
    int lda, int ldb, int ldc,
    long long sA, long long sB, long long sC,
    int K, float alpha)
{
    extern __shared__ __half dsm[];

    const __half* Bsel = B;
    if (EPI == EPI_QKV)
        Bsel = (blockIdx.z == 0) ? g_Wq : (blockIdx.z == 1) ? g_Wk : g_Wv;

    const __half* Ab = A + (long long)blockIdx.z * sA + (long long)blockIdx.y * BM * lda;
    const __half* Bb = Bsel + ((EPI == EPI_QKV) ? 0 : (long long)blockIdx.z * sB)
                            + (long long)blockIdx.x * BN * ldb;

    const int tid  = threadIdx.x;
    const int lane = tid & 31;
    const int warp = tid >> 5;      // 0..3
    const int wm = warp >> 1;       // 0..1
    const int wn = warp & 1;        // 0..1
    const int g  = lane >> 2;       // 0..7
    const int tg = lane & 3;        // 0..3

    // Superstage slot pointers (rotated each epoch; slot0 = compute, slot2 = fill)
    __half* sa0 = dsm;
    __half* sa1 = sa0 + ASUP;
    __half* sa2 = sa1 + ASUP;
    __half* sb0 = dsm + 3 * ASUP;
    __half* sb1 = sb0 + BSUP;
    __half* sb2 = sb1 + BSUP;

    // Loader: row = (tid>>2) + 32*i (i=0..3), 16B chunk = (tid&3)*8 halves
    const int lr  = tid >> 2;
    const int lc8 = (tid & 3) * 8;
    const __half* aptr = Ab + (long long)lr * lda + lc8;
    const __half* bptr = Bb + (long long)lr * ldb + lc8;

    float acc[4][8][4];
    #pragma unroll
    for (int i = 0; i < 4; i++)
        #pragma unroll
        for (int j = 0; j < 8; j++)
            #pragma unroll
            for (int c = 0; c < 4; c++) acc[i][j][c] = 0.f;

    const int NE = K / (2 * BK);   // epochs (superstages): 16 or 64

    // Load one superstage (2 sub-stages) into (sa, sb); one commit group.
    auto load = [&](const __half* ga, const __half* gb, __half* sa, __half* sb,
                    bool pred) {
        if (pred) {
            #pragma unroll
            for (int s = 0; s < 2; s++) {
                #pragma unroll
                for (int i = 0; i < 4; i++)
                    cp16s(&sa[s * ASTAGE + (lr + i * 32) * BK + lc8],
                          ga + s * BK + (long long)(i * 32) * lda);
                #pragma unroll
                for (int i = 0; i < 4; i++)
                    cp16s(&sb[s * BSTAGE + (lr + i * 32) * BK + lc8],
                          gb + s * BK + (long long)(i * 32) * ldb);
            }
        }
        asm volatile("cp.async.commit_group;");
    };

    // Prologue: superstages k0 -> slot0, k1 -> slot1
    load(aptr,          bptr,          sa0, sb0, true);
    load(aptr + 2 * BK, bptr + 2 * BK, sa1, sb1, true);
    aptr += 4 * BK;
    bptr += 4 * BK;

    asm volatile("cp.async.wait_group 0;");
    __syncthreads();

    // Preload B fragments for epoch 0, sub-stage 0
    uint4 bb_cur[8];
    #pragma unroll
    for (int nt = 0; nt < 8; nt++)
        bb_cur[nt] = *(const uint4*)&sb0[(wn * 64 + nt * 8 + g) * BK + tg * 8];

    for (int e = 0; e < NE; e++) {
        // Groups pending: only the one issued at e-1 (k e+1) — wait for it so
        // slot1 (cross-epoch bb prefetch source) is resident; sync makes all
        // threads' copies visible AND protects slot2 (consumed at e-1) overwrite.
        asm volatile("cp.async.wait_group 0;");
        __syncthreads();

        load(aptr, bptr, sa2, sb2, e + 2 < NE);
        aptr += 2 * BK;
        bptr += 2 * BK;

        #pragma unroll
        for (int sub = 0; sub < 2; sub++) {
            const __half* as = sa0 + sub * ASTAGE;
            // next B fragments: sub0 -> slot0 sub1; sub1 -> slot1 sub0
            // (at e = NE-1, sub1 reads stale smem — dead value, never used)
            const __half* bsn = sub ? sb1 : (sb0 + BSTAGE);

            uint4 bb_nxt[8];
            #pragma unroll
            for (int nt = 0; nt < 8; nt++)
                bb_nxt[nt] = *(const uint4*)&bsn[(wn * 64 + nt * 8 + g) * BK + tg * 8];

            #pragma unroll
            for (int mt = 0; mt < 4; mt++) {
                int r0 = wm * 64 + mt * 16;
                uint4 alo = *(const uint4*)&as[(r0 + g    ) * BK + tg * 8];
                uint4 ahi = *(const uint4*)&as[(r0 + g + 8) * BK + tg * 8];
                #pragma unroll
                for (int nt = 0; nt < 8; nt++)
                    MMA_F16(acc[mt][nt], alo.x, ahi.x, alo.y, ahi.y,
                            bb_cur[nt].x, bb_cur[nt].y);
                #pragma unroll
                for (int nt = 0; nt < 8; nt++)
                    MMA_F16(acc[mt][nt], alo.z, ahi.z, alo.w, ahi.w,
                            bb_cur[nt].z, bb_cur[nt].w);
            }

            #pragma unroll
            for (int nt = 0; nt < 8; nt++) bb_cur[nt] = bb_nxt[nt];
        }

        // Rotate slots: 0 <- 1 <- 2 <- 0
        __half* ta = sa0; sa0 = sa1; sa1 = sa2; sa2 = ta;
        __half* tb = sb0; sb0 = sb1; sb1 = sb2; sb2 = tb;
    }

    // ---------------- Epilogue ----------------
    const int zq = (EPI == EPI_QKV) ? (int)blockIdx.z : 0;
    __half* Cq = nullptr;
    int ldq = ldc;
    if (EPI == EPI_QKV) {
        Cq = (zq == 0) ? g_Q : (zq == 1) ? g_K : g_Vt;
        ldq = (zq == 2) ? BT : DIM;
    }

    #pragma unroll
    for (int mt = 0; mt < 4; mt++) {
        int row0 = blockIdx.y * BM + wm * 64 + mt * 16 + g;   // within batch matrix
        float plo = 0.f, phi = 0.f;                            // EPI_EXP row partials
        float inv0 = 1.f, inv1 = 1.f;
        if (EPI == EPI_NORM) {
            const float* invp = aux + (long long)blockIdx.z * SEQ;
            inv0 = __ldg(&invp[row0]);
            inv1 = __ldg(&invp[row0 + 8]);
        }
        #pragma unroll
        for (int nt = 0; nt < 8; nt++) {
            int col0 = blockIdx.x * BN + wn * 64 + nt * 8 + 2 * tg;
            float v0 = acc[mt][nt][0] * alpha;
            float v1 = acc[mt][nt][1] * alpha;
            float v2 = acc[mt][nt][2] * alpha;
            float v3 = acc[mt][nt][3] * alpha;

            if (EPI == EPI_QKV) {
                if (zq < 2) {
                    __half2 h01 = __floats2half2_rn(v0, v1);
                    __half2 h23 = __floats2half2_rn(v2, v3);
                    *(__half2*)&Cq[(long long)(row0    ) * ldq + col0] = h01;
                    *(__half2*)&Cq[(long long)(row0 + 8) * ldq + col0] = h23;
                } else {
                    Cq[(long long)(col0    ) * ldq + row0    ] = __float2half_rn(v0);
                    Cq[(long long)(col0 + 1) * ldq + row0    ] = __float2half_rn(v1);
                    Cq[(long long)(col0    ) * ldq + row0 + 8] = __float2half_rn(v2);
                    Cq[(long long)(col0 + 1) * ldq + row0 + 8] = __float2half_rn(v3);
                }
            } else if (EPI == EPI_EXP) {
                __half* C = (__half*)Cv + (long long)blockIdx.z * sC;
                float e0 = __expf(fminf(v0, 11.f));
                float e1 = __expf(fminf(v1, 11.f));
                float e2 = __expf(fminf(v2, 11.f));
                float e3 = __expf(fminf(v3, 11.f));
                plo += e0 + e1; phi += e2 + e3;
                __half2 h01 = __floats2half2_rn(e0, e1);
                __half2 h23 = __floats2half2_rn(e2, e3);
                *(__half2*)&C[(long long)(row0    ) * ldc + col0] = h01;
                *(__half2*)&C[(long long)(row0 + 8) * ldc + col0] = h23;
            } else { // EPI_NORM
                float* C = (float*)Cv + (long long)blockIdx.z * sC;
                *(float2*)&C[(long long)(row0    ) * ldc + col0] =
                    make_float2(v0 * inv0, v1 * inv0);
                *(float2*)&C[(long long)(row0 + 8) * ldc + col0] =
                    make_float2(v2 * inv1, v3 * inv1);
            }
        }
        if (EPI == EPI_EXP) {
            // quad reduce across tg (lane bits 0,1), then leader stores partials.
            plo += __shfl_xor_sync(0xffffffffu, plo, 1);
            plo += __shfl_xor_sync(0xffffffffu, plo, 2);
            phi += __shfl_xor_sync(0xffffffffu, phi, 1);
            phi += __shfl_xor_sync(0xffffffffu, phi, 2);
            if (tg == 0) {
                long long slot = (long long)(blockIdx.x * 2 + wn) * BT
                               + (long long)blockIdx.z * SEQ;
                aux[slot + row0    ] = plo;
                aux[slot + row0 + 8] = phi;
            }
        }
    }
}

extern "C" void kernel_launch(void* const* d_in, const int* in_sizes, int n_in,
                              void* d_out, int out_size) {
    const float* x  = (const float*)d_in[0];
    const float* Wq = (const float*)d_in[1];
    const float* Wk = (const float*)d_in[2];
    const float* Wv = (const float*)d_in[3];
    float* out = (float*)d_out;

    __half *pX, *pQ, *pK, *pVt, *pP;
    float *pPsum, *pInv;
    cudaGetSymbolAddress((void**)&pX,  g_X);
    cudaGetSymbolAddress((void**)&pQ,  g_Q);
    cudaGetSymbolAddress((void**)&pK,  g_K);
    cudaGetSymbolAddress((void**)&pVt, g_Vt);
    cudaGetSymbolAddress((void**)&pP,  g_P);
    cudaGetSymbolAddress((void**)&pPsum, g_psum);
    cudaGetSymbolAddress((void**)&pInv,  g_inv);

    cudaFuncSetAttribute(gemm_f16<EPI_QKV >, cudaFuncAttributeMaxDynamicSharedMemorySize, SMEM_DYN);
    cudaFuncSetAttribute(gemm_f16<EPI_EXP >, cudaFuncAttributeMaxDynamicSharedMemorySize, SMEM_DYN);
    cudaFuncSetAttribute(gemm_f16<EPI_NORM>, cudaFuncAttributeMaxDynamicSharedMemorySize, SMEM_DYN);

    const long long nX = (long long)BT * DIM;
    const long long strideQK = (long long)SEQ * DIM;
    const long long strideS  = (long long)SEQ * SEQ;

    // Convert inputs to fp16 (x + all three weights in 2 launches)
    to_half_kernel<<<(unsigned)(nX / 4 / 256), 256>>>(x, pX, nX);
    w_to_half_kernel<<<3 * 1024, 256>>>(Wq, Wk, Wv);

    // Fused QKV projections: one launch, z selects weight + destination.
    dim3 gProj(DIM / BN, BT / BM, 3);
    gemm_f16<EPI_QKV><<<gProj, 128, SMEM_DYN>>>(pX, nullptr, nullptr, nullptr,
                                                DIM, DIM, DIM, 0, 0, 0, DIM, 1.0f);

    // Scores + exp fused: P_b = exp(Q_b K_b^T / 32), partial row sums to psum
    dim3 gS(SEQ / BN, SEQ / BM, BATCH);
    gemm_f16<EPI_EXP><<<gS, 128, SMEM_DYN>>>(pQ, pK, pP, pPsum, DIM, DIM, SEQ,
                                             strideQK, strideQK, strideS, DIM, 0.03125f);

    // Row sums -> reciprocals
    rowinv_kernel<<<BT / 256, 256>>>(pPsum, pInv);

    // Output: O_b = (P_b V_b) * inv_rowsum -> f32
    dim3 gO(DIM / BN, SEQ / BM, BATCH);
    gemm_f16<EPI_NORM><<<gO, 128, SMEM_DYN>>>(pP, pVt, out, pInv, SEQ, BT, DIM,
                                              strideS, (long long)SEQ, (long long)SEQ * DIM,
                                              SEQ, 1.0f);
}

// round 12
// speedup vs baseline: 1.0332x; 1.0332x over previous
#include <cuda_runtime.h>
#include <cuda_fp16.h>
#include <cstdint>

// Problem constants
#define BATCH 4
#define SEQ   4096
#define DIM   1024
#define BT    (BATCH * SEQ)      // 16384

// GEMM tile config (fp16 operands, f32 accum)
// CTA tile 128x128, 4 warps, warp tile 64x64, BK=32, 5-slot cp.async pipeline
// (wait_group 2 => two loads always in flight), B-fragment double buffering.
#define BM 128
#define BN 128
#define BK 32
#define NST 5
#define ASTAGE (BM * BK)                       // halves per A stage (8KB)
#define BSTAGE (BN * BK)
#define SMEM_DYN (NST * (ASTAGE + BSTAGE) * 2) // 80 KB

// Epilogue modes
#define EPI_EXP   3   // exp -> fp16 out + deterministic partial row sums
#define EPI_NORM  4   // f32 out scaled by per-row inv sum
#define EPI_QKV   5   // fused QKV projection: z selects W + destination (z==2 transposed)

// Scratch (allocation-free rule: __device__ globals)
__device__ __half g_X [(long long)BT*DIM];
__device__ __half g_Wq[(long long)DIM*DIM];
__device__ __half g_Wk[(long long)DIM*DIM];
__device__ __half g_Wv[(long long)DIM*DIM];
__device__ __half g_Q [(long long)BT*DIM];
__device__ __half g_K [(long long)BT*DIM];
__device__ __half g_Vt[(long long)BT*DIM];         // [e][b*SEQ + t], ld = BT
__device__ __half g_P [(long long)BATCH*SEQ*SEQ];  // unnormalized exp probs, fp16
__device__ float  g_psum[64LL * BT];               // partial row sums [slot][row]
__device__ float  g_inv [BT];                      // 1 / row sum

__device__ __forceinline__ void cp16s(void* sm, const void* gm) {
    unsigned s = (unsigned)__cvta_generic_to_shared(sm);
    asm volatile("cp.async.cg.shared.global [%0], [%1], 16;" :: "r"(s), "l"(gm));
}

#define MMA_F16(acc, a0, a1, a2, a3, b0, b1)                                \
    asm volatile(                                                           \
        "mma.sync.aligned.m16n8k16.row.col.f32.f16.f16.f32 "                \
        "{%0,%1,%2,%3}, {%4,%5,%6,%7}, {%8,%9}, {%0,%1,%2,%3};"             \
        : "+f"((acc)[0]), "+f"((acc)[1]), "+f"((acc)[2]), "+f"((acc)[3])    \
        : "r"(a0), "r"(a1), "r"(a2), "r"(a3), "r"(b0), "r"(b1))

// f32 -> f16 conversion, 4 elems/thread (x input)
__global__ void to_half_kernel(const float* __restrict__ in, __half* __restrict__ out,
                               long long n) {
    long long i = ((long long)blockIdx.x * blockDim.x + threadIdx.x) * 4;
    if (i < n) {
        float4 v = *(const float4*)(in + i);
        __half2 h0 = __floats2half2_rn(v.x, v.y);
        __half2 h1 = __floats2half2_rn(v.z, v.w);
        *(uint2*)(out + i) = make_uint2(*(uint32_t*)&h0, *(uint32_t*)&h1);
    }
}

// All three weight converts in one launch: 1024 blocks per weight (1M elems each).
__global__ void w_to_half_kernel(const float* __restrict__ Wq,
                                 const float* __restrict__ Wk,
                                 const float* __restrict__ Wv) {
    int seg = blockIdx.x >> 10;
    const float* in = (seg == 0) ? Wq : (seg == 1) ? Wk : Wv;
    __half* out = (seg == 0) ? g_Wq : (seg == 1) ? g_Wk : g_Wv;
    long long i = (((long long)(blockIdx.x & 1023)) * 256 + threadIdx.x) * 4;
    float4 v = *(const float4*)(in + i);
    __half2 h0 = __floats2half2_rn(v.x, v.y);
    __half2 h1 = __floats2half2_rn(v.z, v.w);
    *(uint2*)(out + i) = make_uint2(*(uint32_t*)&h0, *(uint32_t*)&h1);
}

// Sum 64 partials per row, store reciprocal. grid = BT/256, block 256.
__global__ void rowinv_kernel(const float* __restrict__ psum, float* __restrict__ inv) {
    int row = blockIdx.x * 256 + threadIdx.x;
    float s = 0.f;
    #pragma unroll
    for (int j = 0; j < 64; j++) s += psum[(long long)j * BT + row];
    inv[row] = 1.f / s;
}

// C[M,N] = alpha * A[M,K] * B[N,K]^T, fp16 operands (K-contiguous), f32 accumulate.
// k-permutation trick: one LDS.128 per row gives thread tg k = {8tg..8tg+7};
// mma step0 uses {8tg..8tg+3}, step1 uses {8tg+4..8tg+7}; A/B slots agree.
template<int EPI>
__global__ void __launch_bounds__(128, 2) gemm_f16(
    const __half* __restrict__ A, const __half* __restrict__ B, void* __restrict__ Cv,
    float* __restrict__ aux,   // EPI_EXP: psum base; EPI_NORM: inv base
    int lda, int ldb, int ldc,
    long long sA, long long sB, long long sC,
    int K, float alpha)
{
    extern __shared__ __half dsm[];

    const __half* Bsel = B;
    if (EPI == EPI_QKV)
        Bsel = (blockIdx.z == 0) ? g_Wq : (blockIdx.z == 1) ? g_Wk : g_Wv;

    const __half* Ab = A + (long long)blockIdx.z * sA + (long long)blockIdx.y * BM * lda;
    const __half* Bb = Bsel + ((EPI == EPI_QKV) ? 0 : (long long)blockIdx.z * sB)
                            + (long long)blockIdx.x * BN * ldb;

    const int tid  = threadIdx.x;
    const int lane = tid & 31;
    const int warp = tid >> 5;      // 0..3
    const int wm = warp >> 1;       // 0..1
    const int wn = warp & 1;        // 0..1
    const int g  = lane >> 2;       // 0..7
    const int tg = lane & 3;        // 0..3

    // Slot pointers. At start of iter kt: p0->kt (compute), p1->kt+1 (bb prefetch),
    // p2->kt+2, p3->kt+3 (in flight), p4->kt-1 (consumed; refilled with kt+4).
    __half* pa[NST];
    __half* pb[NST];
    #pragma unroll
    for (int s = 0; s < NST; s++) {
        pa[s] = dsm + s * ASTAGE;
        pb[s] = dsm + NST * ASTAGE + s * BSTAGE;
    }

    // Loader: row = (tid>>2) + 32*i (i=0..3), 16B chunk = (tid&3)*8 halves
    const int lr  = tid >> 2;
    const int lc8 = (tid & 3) * 8;
    const __half* aptr = Ab + (long long)lr * lda + lc8;
    const __half* bptr = Bb + (long long)lr * ldb + lc8;

    float acc[4][8][4];
    #pragma unroll
    for (int i = 0; i < 4; i++)
        #pragma unroll
        for (int j = 0; j < 8; j++)
            #pragma unroll
            for (int c = 0; c < 4; c++) acc[i][j][c] = 0.f;

    const int KT = K / BK;   // 32 or 128

    auto load = [&](const __half* ga, const __half* gb, __half* sa, __half* sb,
                    bool pred) {
        if (pred) {
            #pragma unroll
            for (int i = 0; i < 4; i++)
                cp16s(&sa[(lr + i * 32) * BK + lc8], ga + (long long)(i * 32) * lda);
            #pragma unroll
            for (int i = 0; i < 4; i++)
                cp16s(&sb[(lr + i * 32) * BK + lc8], gb + (long long)(i * 32) * ldb);
        }
        asm volatile("cp.async.commit_group;");
    };

    // Prologue: stages 0..3 into p0..p3
    #pragma unroll
    for (int s = 0; s < 4; s++) {
        load(aptr, bptr, pa[s], pb[s], true);
        aptr += BK;
        bptr += BK;
    }

    asm volatile("cp.async.wait_group 2;");  // stages 0,1 complete
    __syncthreads();

    // Preload B fragments for kt = 0 (stage 0)
    uint4 bb_cur[8];
    #pragma unroll
    for (int nt = 0; nt < 8; nt++)
        bb_cur[nt] = *(const uint4*)&pb[0][(wn * 64 + nt * 8 + g) * BK + tg * 8];

    for (int kt = 0; kt < KT; kt++) {
        // All but the 2 newest groups complete => stage kt+1 resident (bb_nxt src).
        asm volatile("cp.async.wait_group 2;");
        __syncthreads();   // visibility + protects p4 (stage kt-1) overwrite

        load(aptr, bptr, pa[4], pb[4], kt + 4 < KT);
        aptr += BK;
        bptr += BK;

        const __half* as  = pa[0];
        const __half* bsn = pb[1];

        uint4 bb_nxt[8];
        #pragma unroll
        for (int mt = 0; mt < 4; mt++) {
            int r0 = wm * 64 + mt * 16;
            uint4 alo = *(const uint4*)&as[(r0 + g    ) * BK + tg * 8];
            uint4 ahi = *(const uint4*)&as[(r0 + g + 8) * BK + tg * 8];
            #pragma unroll
            for (int nt = 0; nt < 8; nt++)
                MMA_F16(acc[mt][nt], alo.x, ahi.x, alo.y, ahi.y,
                        bb_cur[nt].x, bb_cur[nt].y);
            // Interleave the next-iteration B prefetch after the first MMA block
            // to shorten the post-barrier LDS convoy.
            if (mt == 0) {
                #pragma unroll
                for (int nt = 0; nt < 8; nt++)
                    bb_nxt[nt] =
                        *(const uint4*)&bsn[(wn * 64 + nt * 8 + g) * BK + tg * 8];
            }
            #pragma unroll
            for (int nt = 0; nt < 8; nt++)
                MMA_F16(acc[mt][nt], alo.z, ahi.z, alo.w, ahi.w,
                        bb_cur[nt].z, bb_cur[nt].w);
        }

        #pragma unroll
        for (int nt = 0; nt < 8; nt++) bb_cur[nt] = bb_nxt[nt];

        // Rotate slots left: p0 <- p1 <- ... <- p4 <- p0
        __half* ta = pa[0]; __half* tb = pb[0];
        #pragma unroll
        for (int s = 0; s < NST - 1; s++) { pa[s] = pa[s + 1]; pb[s] = pb[s + 1]; }
        pa[NST - 1] = ta; pb[NST - 1] = tb;
    }

    // ---------------- Epilogue ----------------
    const int zq = (EPI == EPI_QKV) ? (int)blockIdx.z : 0;
    __half* Cq = nullptr;
    int ldq = ldc;
    if (EPI == EPI_QKV) {
        Cq = (zq == 0) ? g_Q : (zq == 1) ? g_K : g_Vt;
        ldq = (zq == 2) ? BT : DIM;
    }

    #pragma unroll
    for (int mt = 0; mt < 4; mt++) {
        int row0 = blockIdx.y * BM + wm * 64 + mt * 16 + g;   // within batch matrix
        float plo = 0.f, phi = 0.f;                            // EPI_EXP row partials
        float inv0 = 1.f, inv1 = 1.f;
        if (EPI == EPI_NORM) {
            const float* invp = aux + (long long)blockIdx.z * SEQ;
            inv0 = __ldg(&invp[row0]);
            inv1 = __ldg(&invp[row0 + 8]);
        }
        #pragma unroll
        for (int nt = 0; nt < 8; nt++) {
            int col0 = blockIdx.x * BN + wn * 64 + nt * 8 + 2 * tg;
            float v0 = acc[mt][nt][0] * alpha;
            float v1 = acc[mt][nt][1] * alpha;
            float v2 = acc[mt][nt][2] * alpha;
            float v3 = acc[mt][nt][3] * alpha;

            if (EPI == EPI_QKV) {
                if (zq < 2) {
                    __half2 h01 = __floats2half2_rn(v0, v1);
                    __half2 h23 = __floats2half2_rn(v2, v3);
                    *(__half2*)&Cq[(long long)(row0    ) * ldq + col0] = h01;
                    *(__half2*)&Cq[(long long)(row0 + 8) * ldq + col0] = h23;
                } else {
                    Cq[(long long)(col0    ) * ldq + row0    ] = __float2half_rn(v0);
                    Cq[(long long)(col0 + 1) * ldq + row0    ] = __float2half_rn(v1);
                    Cq[(long long)(col0    ) * ldq + row0 + 8] = __float2half_rn(v2);
                    Cq[(long long)(col0 + 1) * ldq + row0 + 8] = __float2half_rn(v3);
                }
            } else if (EPI == EPI_EXP) {
                __half* C = (__half*)Cv + (long long)blockIdx.z * sC;
                float e0 = __expf(fminf(v0, 11.f));
                float e1 = __expf(fminf(v1, 11.f));
                float e2 = __expf(fminf(v2, 11.f));
                float e3 = __expf(fminf(v3, 11.f));
                plo += e0 + e1; phi += e2 + e3;
                __half2 h01 = __floats2half2_rn(e0, e1);
                __half2 h23 = __floats2half2_rn(e2, e3);
                *(__half2*)&C[(long long)(row0    ) * ldc + col0] = h01;
                *(__half2*)&C[(long long)(row0 + 8) * ldc + col0] = h23;
            } else { // EPI_NORM
                float* C = (float*)Cv + (long long)blockIdx.z * sC;
                *(float2*)&C[(long long)(row0    ) * ldc + col0] =
                    make_float2(v0 * inv0, v1 * inv0);
                *(float2*)&C[(long long)(row0 + 8) * ldc + col0] =
                    make_float2(v2 * inv1, v3 * inv1);
            }
        }
        if (EPI == EPI_EXP) {
            // quad reduce across tg (lane bits 0,1), then leader stores partials.
            plo += __shfl_xor_sync(0xffffffffu, plo, 1);
            plo += __shfl_xor_sync(0xffffffffu, plo, 2);
            phi += __shfl_xor_sync(0xffffffffu, phi, 1);
            phi += __shfl_xor_sync(0xffffffffu, phi, 2);
            if (tg == 0) {
                long long slot = (long long)(blockIdx.x * 2 + wn) * BT
                               + (long long)blockIdx.z * SEQ;
                aux[slot + row0    ] = plo;
                aux[slot + row0 + 8] = phi;
            }
        }
    }
}

extern "C" void kernel_launch(void* const* d_in, const int* in_sizes, int n_in,
                              void* d_out, int out_size) {
    const float* x  = (const float*)d_in[0];
    const float* Wq = (const float*)d_in[1];
    const float* Wk = (const float*)d_in[2];
    const float* Wv = (const float*)d_in[3];
    float* out = (float*)d_out;

    __half *pX, *pQ, *pK, *pVt, *pP;
    float *pPsum, *pInv;
    cudaGetSymbolAddress((void**)&pX,  g_X);
    cudaGetSymbolAddress((void**)&pQ,  g_Q);
    cudaGetSymbolAddress((void**)&pK,  g_K);
    cudaGetSymbolAddress((void**)&pVt, g_Vt);
    cudaGetSymbolAddress((void**)&pP,  g_P);
    cudaGetSymbolAddress((void**)&pPsum, g_psum);
    cudaGetSymbolAddress((void**)&pInv,  g_inv);

    cudaFuncSetAttribute(gemm_f16<EPI_QKV >, cudaFuncAttributeMaxDynamicSharedMemorySize, SMEM_DYN);
    cudaFuncSetAttribute(gemm_f16<EPI_EXP >, cudaFuncAttributeMaxDynamicSharedMemorySize, SMEM_DYN);
    cudaFuncSetAttribute(gemm_f16<EPI_NORM>, cudaFuncAttributeMaxDynamicSharedMemorySize, SMEM_DYN);

    const long long nX = (long long)BT * DIM;
    const long long strideQK = (long long)SEQ * DIM;
    const long long strideS  = (long long)SEQ * SEQ;

    // Convert inputs to fp16 (x + all three weights in 2 launches)
    to_half_kernel<<<(unsigned)(nX / 4 / 256), 256>>>(x, pX, nX);
    w_to_half_kernel<<<3 * 1024, 256>>>(Wq, Wk, Wv);

    // Fused QKV projections: one launch, z selects weight + destination.
    dim3 gProj(DIM / BN, BT / BM, 3);
    gemm_f16<EPI_QKV><<<gProj, 128, SMEM_DYN>>>(pX, nullptr, nullptr, nullptr,
                                                DIM, DIM, DIM, 0, 0, 0, DIM, 1.0f);

    // Scores + exp fused: P_b = exp(Q_b K_b^T / 32), partial row sums to psum
    dim3 gS(SEQ / BN, SEQ / BM, BATCH);
    gemm_f16<EPI_EXP><<<gS, 128, SMEM_DYN>>>(pQ, pK, pP, pPsum, DIM, DIM, SEQ,
                                             strideQK, strideQK, strideS, DIM, 0.03125f);

    // Row sums -> reciprocals
    rowinv_kernel<<<BT / 256, 256>>>(pPsum, pInv);

    // Output: O_b = (P_b V_b) * inv_rowsum -> f32
    dim3 gO(DIM / BN, SEQ / BM, BATCH);
    gemm_f16<EPI_NORM><<<gO, 128, SMEM_DYN>>>(pP, pVt, out, pInv, SEQ, BT, DIM,
                                              strideS, (long long)SEQ, (long long)SEQ * DIM,
                                              SEQ, 1.0f);
}